// round 12
// baseline (speedup 1.0000x reference)
#include <cuda_runtime.h>
#include <cuda_bf16.h>

#define HH 512
#define WW 1024
#define EPSV 1e-5f
#define BPB 64            // reduction blocks per batch
#define RED_THREADS 256
#define VPB ((HH * WW / 4) / BPB)   // float4 vectors per reduction block = 2048

// Scratch (no allocations allowed) — sized for up to 128 batches.
__device__ float g_es [128 * BPB];
__device__ float g_esr[128 * BPB];
__device__ int   g_nvis[128];
__device__ float g_sr  [128];

// ---------------------------------------------------------------------------
// K0: zero the entire output buffer (svf region must start at 0; pts/loss get
// overwritten later). Also zero the per-batch scatter accumulators.
// ---------------------------------------------------------------------------
__global__ void k_zero(float* __restrict__ out, long n4, long n) {
    long i = (long)blockIdx.x * blockDim.x + threadIdx.x;
    float4* o4 = (float4*)out;
    const float4 z = make_float4(0.f, 0.f, 0.f, 0.f);
    long stride = (long)gridDim.x * blockDim.x;
    for (long v = i; v < n4; v += stride) o4[v] = z;
    long tail0 = n4 * 4;
    if (i < n - tail0) out[tail0 + i] = 0.f;
    if (blockIdx.x == 0 && threadIdx.x < 128) {
        g_nvis[threadIdx.x] = 0;
        g_sr[threadIdx.x]   = 0.f;
    }
}

// ---------------------------------------------------------------------------
// K1: per-batch partial reductions of exp_svf and exp_svf*reward.
// grid = (BPB, B). Pure float4 reads, fully coalesced.
// ---------------------------------------------------------------------------
__global__ void k_reduce(const float4* __restrict__ e4,
                         const float4* __restrict__ r4) {
    int b   = blockIdx.y;
    int blk = blockIdx.x;
    long base = (long)b * (HH * WW / 4) + (long)blk * VPB;

    float es = 0.f, esr = 0.f;
#pragma unroll
    for (int k = 0; k < VPB / RED_THREADS; k++) {
        long idx = base + (long)k * RED_THREADS + threadIdx.x;
        float4 e = e4[idx];
        float4 r = r4[idx];
        es  += (e.x + e.y) + (e.z + e.w);
        esr += e.x * r.x + e.y * r.y + e.z * r.z + e.w * r.w;
    }
#pragma unroll
    for (int off = 16; off > 0; off >>= 1) {
        es  += __shfl_down_sync(0xFFFFFFFFu, es,  off);
        esr += __shfl_down_sync(0xFFFFFFFFu, esr, off);
    }
    __shared__ float se[RED_THREADS / 32], sm[RED_THREADS / 32];
    int w = threadIdx.x >> 5;
    if ((threadIdx.x & 31) == 0) { se[w] = es; sm[w] = esr; }
    __syncthreads();
    if (threadIdx.x == 0) {
        float a = 0.f, c = 0.f;
#pragma unroll
        for (int i = 0; i < RED_THREADS / 32; i++) { a += se[i]; c += sm[i]; }
        g_es [b * BPB + blk] = a;
        g_esr[b * BPB + blk] = c;
    }
}

// ---------------------------------------------------------------------------
// Shared point-interpolation helper. Mul-then-add (no FMA) to match JAX's
// start + t*(end-start) rounding so int truncation picks the same cell.
// ---------------------------------------------------------------------------
__device__ __forceinline__ void interp_point(const float* __restrict__ gt,
                                             int b, int p, int T, int Npts,
                                             int ms, float& px, float& py) {
    if (p == Npts - 1) {
        const float* g = gt + ((long)b * T + (T - 1)) * 9;
        px = g[2] * 0.5f;
        py = g[5] * 0.5f;
    } else {
        int s = p / ms;
        int j = p - s * ms;
        const float* g = gt + ((long)b * T + s) * 9;
        float sx = g[2]  * 0.5f, sy = g[5]  * 0.5f;
        float ex = g[11] * 0.5f, ey = g[14] * 0.5f;
        float t = (ms > 1) ? (float)j / (float)(ms - 1) : 0.f;
        px = __fadd_rn(sx, __fmul_rn(t, __fsub_rn(ex, sx)));
        py = __fadd_rn(sy, __fmul_rn(t, __fsub_rn(ey, sy)));
    }
}

__device__ __forceinline__ long point_cell(int b, float px, float py) {
    int xi = (int)fminf(fmaxf(px, 0.f), (float)(HH - 1));
    int yi = (int)fminf(fmaxf(py, 0.f), (float)(WW - 1));
    return (long)b * (HH * WW) + (long)xi * WW + yi;
}

// ---------------------------------------------------------------------------
// K2: one thread per interpolated point. Writes interp_pts output, scatters
// visitation (dedup via atomicExch), accumulates per-batch nvis and
// sum(reward @ visited cells).
// ---------------------------------------------------------------------------
__global__ void k_points(const float* __restrict__ gt,
                         const float* __restrict__ rew,
                         float* __restrict__ svf,
                         float* __restrict__ pts_out,
                         int B, int T, int Npts, int ms) {
    int idx = blockIdx.x * blockDim.x + threadIdx.x;
    if (idx >= B * Npts) return;
    int b = idx / Npts;
    int p = idx - b * Npts;

    float px, py;
    interp_point(gt, b, p, T, Npts, ms, px, py);

    pts_out[(long)idx * 2]     = px;
    pts_out[(long)idx * 2 + 1] = py;

    long cell = point_cell(b, px, py);
    float old = atomicExch(&svf[cell], 1.0f);
    if (old == 0.0f) {
        atomicAdd(&g_nvis[b], 1);
        atomicAdd(&g_sr[b], rew[cell]);
    }
}

// ---------------------------------------------------------------------------
// K3: overwrite each visited cell with its normalized value 1/(nvis+eps).
// Idempotent stores; every visited cell is the image of >=1 point.
// ---------------------------------------------------------------------------
__global__ void k_scale(const float* __restrict__ gt,
                        float* __restrict__ svf,
                        int B, int T, int Npts, int ms) {
    int idx = blockIdx.x * blockDim.x + threadIdx.x;
    if (idx >= B * Npts) return;
    int b = idx / Npts;
    int p = idx - b * Npts;

    float px, py;
    interp_point(gt, b, p, T, Npts, ms, px, py);
    long cell = point_cell(b, px, py);
    svf[cell] = 1.0f / ((float)g_nvis[b] + EPSV);
}

// ---------------------------------------------------------------------------
// K4: final deterministic reduction -> scalar loss.
// loss = mean_b( esr_b/(es_b+eps) ) - mean_b( sr_b/(nvis_b+eps) )
// ---------------------------------------------------------------------------
__global__ void k_final(float* __restrict__ out_loss, int B) {
    int b = threadIdx.x;
    float et = 0.f, st = 0.f;
    if (b < B) {
        float es = 0.f, esr = 0.f;
#pragma unroll 8
        for (int i = 0; i < BPB; i++) {
            es  += g_es [b * BPB + i];
            esr += g_esr[b * BPB + i];
        }
        et = esr / (es + EPSV);
        st = g_sr[b] / ((float)g_nvis[b] + EPSV);
    }
    __shared__ float se[128], ss[128];
    se[threadIdx.x] = et;
    ss[threadIdx.x] = st;
    __syncthreads();
#pragma unroll
    for (int off = 64; off > 0; off >>= 1) {
        if (threadIdx.x < off) {
            se[threadIdx.x] += se[threadIdx.x + off];
            ss[threadIdx.x] += ss[threadIdx.x + off];
        }
        __syncthreads();
    }
    if (threadIdx.x == 0)
        out_loss[0] = (se[0] - ss[0]) / (float)B;
}

// ---------------------------------------------------------------------------
extern "C" void kernel_launch(void* const* d_in, const int* in_sizes, int n_in,
                              void* d_out, int out_size) {
    const float* gt      = (const float*)d_in[0];  // (B,T,3,3)
    const float* exp_svf = (const float*)d_in[1];  // (B,H,W)
    const float* rew     = (const float*)d_in[2];  // (B,H,W)
    float* out = (float*)d_out;

    int B = in_sizes[1] / (HH * WW);
    int T = in_sizes[0] / (B * 9);
    long grid_elems = (long)B * HH * WW;
    // out layout: [loss(1)][svf(B*H*W)][interp_pts(B*Npts*2)]
    int Npts = (int)(((long)out_size - 1 - grid_elems) / (2L * B));
    int ms = (T > 1 && Npts > 1) ? (Npts - 1) / (T - 1) : 1;
    if (ms < 1) ms = 1;

    float* svf = out + 1;
    float* pts = out + 1 + grid_elems;

    long n  = (long)out_size;
    long n4 = n / 4;  // out base is 256B-aligned -> float4 OK

    k_zero<<<4096, 256>>>(out, n4, n);

    dim3 rg(BPB, B);
    k_reduce<<<rg, RED_THREADS>>>((const float4*)exp_svf, (const float4*)rew);

    int tot = B * Npts;
    int pblocks = (tot + 255) / 256;
    k_points<<<pblocks, 256>>>(gt, rew, svf, pts, B, T, Npts, ms);
    k_scale<<<pblocks, 256>>>(gt, svf, B, T, Npts, ms);
    k_final<<<1, 128>>>(out, B);
}

// round 15
// speedup vs baseline: 1.1299x; 1.1299x over previous
#include <cuda_runtime.h>
#include <cuda_bf16.h>

#define HH 512
#define WW 1024
#define EPSV 1e-5f
#define BPB 64            // reduction blocks per batch
#define RED_THREADS 256
#define VPB ((HH * WW / 4) / BPB)   // float4 vectors per reduction block = 2048
#define RED_ITERS (VPB / RED_THREADS)  // 8

// Scratch (no allocations allowed) — sized for up to 128 batches.
__device__ float g_es [128 * BPB];
__device__ float g_esr[128 * BPB];
__device__ int   g_nvis[128];
__device__ float g_sr  [128];

// ---------------------------------------------------------------------------
// K_MAIN: fused (a) zero entire output buffer, (b) per-batch partial
// reductions of exp_svf and exp_svf*reward. The two jobs are independent, so
// interleaving them keeps read AND write streams in flight simultaneously
// instead of two serial pure-read / pure-write kernels.
// grid = (BPB, B). Streaming cache hints: every byte is touched once.
// NOTE: o4 (float4 view of out) is safe — out base is 256B-aligned.
// ---------------------------------------------------------------------------
__global__ void k_main(const float4* __restrict__ e4,
                       const float4* __restrict__ r4,
                       float4* __restrict__ o4,
                       float* __restrict__ out,
                       long n4, long n, long c4) {
    int b   = blockIdx.y;
    int blk = blockIdx.x;
    int gid = b * BPB + blk;
    long base  = (long)b * (HH * WW / 4) + (long)blk * VPB;
    long zbase = (long)gid * c4;
    long zend  = zbase + c4; if (zend > n4) zend = n4;

    const float4 z = make_float4(0.f, 0.f, 0.f, 0.f);
    float es = 0.f, esr = 0.f;

#pragma unroll
    for (int k = 0; k < RED_ITERS; k++) {
        long idx = base + (long)k * RED_THREADS + threadIdx.x;
        float4 e = __ldcs(&e4[idx]);
        float4 r = __ldcs(&r4[idx]);
        // interleaved zero-store for this block's output chunk
        long zi = zbase + (long)k * RED_THREADS + threadIdx.x;
        if (zi < zend) __stcs(&o4[zi], z);
        es  += (e.x + e.y) + (e.z + e.w);
        esr += e.x * r.x + e.y * r.y + e.z * r.z + e.w * r.w;
    }
    // leftover zero iterations (chunk may exceed RED_ITERS*256 vectors)
    for (long zi = zbase + (long)RED_ITERS * RED_THREADS + threadIdx.x;
         zi < zend; zi += RED_THREADS)
        __stcs(&o4[zi], z);

    // scalar tail of the output buffer (< 4 floats)
    if (gid == 0 && threadIdx.x < (int)(n - n4 * 4))
        out[n4 * 4 + threadIdx.x] = 0.f;
    // per-batch scatter accumulators
    if (gid == gridDim.x * gridDim.y - 1 && threadIdx.x < 128) {
        g_nvis[threadIdx.x] = 0;
        g_sr[threadIdx.x]   = 0.f;
    }

#pragma unroll
    for (int off = 16; off > 0; off >>= 1) {
        es  += __shfl_down_sync(0xFFFFFFFFu, es,  off);
        esr += __shfl_down_sync(0xFFFFFFFFu, esr, off);
    }
    __shared__ float se[RED_THREADS / 32], sm[RED_THREADS / 32];
    int w = threadIdx.x >> 5;
    if ((threadIdx.x & 31) == 0) { se[w] = es; sm[w] = esr; }
    __syncthreads();
    if (threadIdx.x == 0) {
        float a = 0.f, c = 0.f;
#pragma unroll
        for (int i = 0; i < RED_THREADS / 32; i++) { a += se[i]; c += sm[i]; }
        g_es [b * BPB + blk] = a;
        g_esr[b * BPB + blk] = c;
    }
}

// ---------------------------------------------------------------------------
// Point interpolation. Mul-then-add (no FMA) to match JAX's
// start + t*(end-start) rounding so int truncation picks the same cell.
// ---------------------------------------------------------------------------
__device__ __forceinline__ void interp_point(const float* __restrict__ gt,
                                             int b, int p, int T, int Npts,
                                             int ms, float& px, float& py) {
    if (p == Npts - 1) {
        const float* g = gt + ((long)b * T + (T - 1)) * 9;
        px = g[2] * 0.5f;
        py = g[5] * 0.5f;
    } else {
        int s = p / ms;
        int j = p - s * ms;
        const float* g = gt + ((long)b * T + s) * 9;
        float sx = g[2]  * 0.5f, sy = g[5]  * 0.5f;
        float ex = g[11] * 0.5f, ey = g[14] * 0.5f;
        float t = (ms > 1) ? (float)j / (float)(ms - 1) : 0.f;
        px = __fadd_rn(sx, __fmul_rn(t, __fsub_rn(ex, sx)));
        py = __fadd_rn(sy, __fmul_rn(t, __fsub_rn(ey, sy)));
    }
}

__device__ __forceinline__ long point_cell(int b, float px, float py) {
    int xi = (int)fminf(fmaxf(px, 0.f), (float)(HH - 1));
    int yi = (int)fminf(fmaxf(py, 0.f), (float)(WW - 1));
    return (long)b * (HH * WW) + (long)xi * WW + yi;
}

// ---------------------------------------------------------------------------
// K_POINTS: one thread per interpolated point. Writes interp_pts output,
// scatters visitation (dedup via atomicExch), accumulates per-batch nvis and
// sum(reward @ visited cells).
// ---------------------------------------------------------------------------
__global__ void k_points(const float* __restrict__ gt,
                         const float* __restrict__ rew,
                         float* __restrict__ svf,
                         float* __restrict__ pts_out,
                         int B, int T, int Npts, int ms) {
    int idx = blockIdx.x * blockDim.x + threadIdx.x;
    if (idx >= B * Npts) return;
    int b = idx / Npts;
    int p = idx - b * Npts;

    float px, py;
    interp_point(gt, b, p, T, Npts, ms, px, py);

    pts_out[(long)idx * 2]     = px;
    pts_out[(long)idx * 2 + 1] = py;

    long cell = point_cell(b, px, py);
    float old = atomicExch(&svf[cell], 1.0f);
    if (old == 0.0f) {
        atomicAdd(&g_nvis[b], 1);
        atomicAdd(&g_sr[b], rew[cell]);
    }
}

// ---------------------------------------------------------------------------
// K_SCALE: overwrite each visited cell with 1/(nvis+eps). Re-reads the
// already-computed points from pts_out with SCALAR loads — pts base sits at
// an ODD float offset (out+1+grid_elems), so vector (float2) loads would be
// misaligned. Two contiguous 4B loads per thread are still fully coalesced.
// Idempotent stores.
// ---------------------------------------------------------------------------
__global__ void k_scale(const float* __restrict__ pts,
                        float* __restrict__ svf,
                        int B, int Npts) {
    int idx = blockIdx.x * blockDim.x + threadIdx.x;
    if (idx >= B * Npts) return;
    int b = idx / Npts;

    float px = pts[(long)idx * 2];
    float py = pts[(long)idx * 2 + 1];
    long cell = point_cell(b, px, py);
    svf[cell] = 1.0f / ((float)g_nvis[b] + EPSV);
}

// ---------------------------------------------------------------------------
// K_FINAL: deterministic reduction -> scalar loss.
// loss = mean_b( esr_b/(es_b+eps) ) - mean_b( sr_b/(nvis_b+eps) )
// ---------------------------------------------------------------------------
__global__ void k_final(float* __restrict__ out_loss, int B) {
    int b = threadIdx.x;
    float et = 0.f, st = 0.f;
    if (b < B) {
        float es = 0.f, esr = 0.f;
#pragma unroll 8
        for (int i = 0; i < BPB; i++) {
            es  += g_es [b * BPB + i];
            esr += g_esr[b * BPB + i];
        }
        et = esr / (es + EPSV);
        st = g_sr[b] / ((float)g_nvis[b] + EPSV);
    }
    __shared__ float se[128], ss[128];
    se[threadIdx.x] = et;
    ss[threadIdx.x] = st;
    __syncthreads();
#pragma unroll
    for (int off = 64; off > 0; off >>= 1) {
        if (threadIdx.x < off) {
            se[threadIdx.x] += se[threadIdx.x + off];
            ss[threadIdx.x] += ss[threadIdx.x + off];
        }
        __syncthreads();
    }
    if (threadIdx.x == 0)
        out_loss[0] = (se[0] - ss[0]) / (float)B;
}

// ---------------------------------------------------------------------------
extern "C" void kernel_launch(void* const* d_in, const int* in_sizes, int n_in,
                              void* d_out, int out_size) {
    const float* gt      = (const float*)d_in[0];  // (B,T,3,3)
    const float* exp_svf = (const float*)d_in[1];  // (B,H,W)
    const float* rew     = (const float*)d_in[2];  // (B,H,W)
    float* out = (float*)d_out;

    int B = in_sizes[1] / (HH * WW);
    int T = in_sizes[0] / (B * 9);
    long grid_elems = (long)B * HH * WW;
    // out layout: [loss(1)][svf(B*H*W)][interp_pts(B*Npts*2)]
    int Npts = (int)(((long)out_size - 1 - grid_elems) / (2L * B));
    int ms = (T > 1 && Npts > 1) ? (Npts - 1) / (T - 1) : 1;
    if (ms < 1) ms = 1;

    float* svf = out + 1;
    float* pts = out + 1 + grid_elems;

    long n  = (long)out_size;
    long n4 = n / 4;                       // out base is 256B-aligned -> float4 OK
    long nblocks = (long)BPB * B;
    long c4 = (n4 + nblocks - 1) / nblocks; // zero-fill chunk per block

    dim3 rg(BPB, B);
    k_main<<<rg, RED_THREADS>>>((const float4*)exp_svf, (const float4*)rew,
                                (float4*)out, out, n4, n, c4);

    int tot = B * Npts;
    int pblocks = (tot + 255) / 256;
    k_points<<<pblocks, 256>>>(gt, rew, svf, pts, B, T, Npts, ms);
    k_scale<<<pblocks, 256>>>(pts, svf, B, Npts);
    k_final<<<1, 128>>>(out, B);
}

// round 16
// speedup vs baseline: 1.1468x; 1.0150x over previous
#include <cuda_runtime.h>
#include <cuda_bf16.h>

#define HH 512
#define WW 1024
#define EPSV 1e-5f
#define BPB 16            // reduction blocks per batch (single-wave grid)
#define RED_THREADS 256
#define VPB ((HH * WW / 4) / BPB)      // float4 vectors per reduction block = 8192
#define RED_ITERS (VPB / RED_THREADS)  // 32

// Scratch (no allocations allowed) — sized for up to 128 batches.
__device__ float g_es [128 * BPB];
__device__ float g_esr[128 * BPB];
__device__ int   g_nvis[128];
__device__ float g_sr  [128];
__device__ int   g_arrive;   // grid-barrier state, reset by k_main each launch
__device__ int   g_flag;

// ---------------------------------------------------------------------------
// K_MAIN: fused (a) zero entire output buffer, (b) per-batch partial
// reductions of exp_svf and exp_svf*reward. Interleaved so read AND write
// streams are in flight simultaneously. grid = (BPB, B) = 1024 blocks ->
// single wave on 148 SMs. Streaming cache hints: every byte touched once.
// ---------------------------------------------------------------------------
__global__ void k_main(const float4* __restrict__ e4,
                       const float4* __restrict__ r4,
                       float4* __restrict__ o4,
                       float* __restrict__ out,
                       long n4, long n, long c4) {
    int b   = blockIdx.y;
    int blk = blockIdx.x;
    int gid = b * BPB + blk;
    long base  = (long)b * (HH * WW / 4) + (long)blk * VPB;
    long zbase = (long)gid * c4;
    long zend  = zbase + c4; if (zend > n4) zend = n4;

    const float4 z = make_float4(0.f, 0.f, 0.f, 0.f);
    float es = 0.f, esr = 0.f;

#pragma unroll 8
    for (int k = 0; k < RED_ITERS; k++) {
        long idx = base + (long)k * RED_THREADS + threadIdx.x;
        float4 e = __ldcs(&e4[idx]);
        float4 r = __ldcs(&r4[idx]);
        long zi = zbase + (long)k * RED_THREADS + threadIdx.x;
        if (zi < zend) __stcs(&o4[zi], z);
        es  += (e.x + e.y) + (e.z + e.w);
        esr += e.x * r.x + e.y * r.y + e.z * r.z + e.w * r.w;
    }
    // leftover zero iterations (chunk slightly exceeds RED_ITERS*256 vectors)
    for (long zi = zbase + (long)RED_ITERS * RED_THREADS + threadIdx.x;
         zi < zend; zi += RED_THREADS)
        __stcs(&o4[zi], z);

    // scalar tail of the output buffer (< 4 floats)
    if (gid == 0 && threadIdx.x < (int)(n - n4 * 4))
        out[n4 * 4 + threadIdx.x] = 0.f;
    // per-batch scatter accumulators + grid-barrier state for k_pts
    if (gid == gridDim.x * gridDim.y - 1) {
        if (threadIdx.x < 128) {
            g_nvis[threadIdx.x] = 0;
            g_sr[threadIdx.x]   = 0.f;
        }
        if (threadIdx.x == 0) { g_arrive = 0; g_flag = 0; }
    }

#pragma unroll
    for (int off = 16; off > 0; off >>= 1) {
        es  += __shfl_down_sync(0xFFFFFFFFu, es,  off);
        esr += __shfl_down_sync(0xFFFFFFFFu, esr, off);
    }
    __shared__ float se[RED_THREADS / 32], sm[RED_THREADS / 32];
    int w = threadIdx.x >> 5;
    if ((threadIdx.x & 31) == 0) { se[w] = es; sm[w] = esr; }
    __syncthreads();
    if (threadIdx.x == 0) {
        float a = 0.f, c = 0.f;
#pragma unroll
        for (int i = 0; i < RED_THREADS / 32; i++) { a += se[i]; c += sm[i]; }
        g_es [b * BPB + blk] = a;
        g_esr[b * BPB + blk] = c;
    }
}

// ---------------------------------------------------------------------------
// Point interpolation. Mul-then-add (no FMA) to match JAX's
// start + t*(end-start) rounding so int truncation picks the same cell.
// ---------------------------------------------------------------------------
__device__ __forceinline__ void interp_point(const float* __restrict__ gt,
                                             int b, int p, int T, int Npts,
                                             int ms, float& px, float& py) {
    if (p == Npts - 1) {
        const float* g = gt + ((long)b * T + (T - 1)) * 9;
        px = g[2] * 0.5f;
        py = g[5] * 0.5f;
    } else {
        int s = p / ms;
        int j = p - s * ms;
        const float* g = gt + ((long)b * T + s) * 9;
        float sx = g[2]  * 0.5f, sy = g[5]  * 0.5f;
        float ex = g[11] * 0.5f, ey = g[14] * 0.5f;
        float t = (ms > 1) ? (float)j / (float)(ms - 1) : 0.f;
        px = __fadd_rn(sx, __fmul_rn(t, __fsub_rn(ex, sx)));
        py = __fadd_rn(sy, __fmul_rn(t, __fsub_rn(ey, sy)));
    }
}

__device__ __forceinline__ long point_cell(int b, float px, float py) {
    int xi = (int)fminf(fmaxf(px, 0.f), (float)(HH - 1));
    int yi = (int)fminf(fmaxf(py, 0.f), (float)(WW - 1));
    return (long)b * (HH * WW) + (long)xi * WW + yi;
}

// ---------------------------------------------------------------------------
// K_PTS: fully fused point pipeline in ONE kernel.
//   Phase 1: per-point interp -> write pts_out -> scatter dedup (atomicExch)
//            -> accumulate per-batch nvis (int) and sum(reward@visited).
//   Grid barrier (spin; all blocks co-resident; state reset by k_main).
//   Phase 2: overwrite each visited cell with 1/(nvis+eps) (px,py in regs).
//   Phase 3: block 0 computes the scalar loss (partials hot in L2).
// No early returns — every thread participates in barriers.
// ---------------------------------------------------------------------------
__global__ void k_pts(const float* __restrict__ gt,
                      const float* __restrict__ rew,
                      float* __restrict__ svf,
                      float* __restrict__ pts_out,
                      float* __restrict__ out_loss,
                      int B, int T, int Npts, int ms) {
    int idx = blockIdx.x * blockDim.x + threadIdx.x;
    int tot = B * Npts;
    bool active = idx < tot;

    float px = 0.f, py = 0.f;
    long cell = 0;
    int b = 0;

    if (active) {
        b = idx / Npts;
        int p = idx - b * Npts;
        interp_point(gt, b, p, T, Npts, ms, px, py);
        pts_out[(long)idx * 2]     = px;
        pts_out[(long)idx * 2 + 1] = py;
        cell = point_cell(b, px, py);
        float old = atomicExch(&svf[cell], 1.0f);
        if (old == 0.0f) {
            atomicAdd(&g_nvis[b], 1);
            atomicAdd(&g_sr[b], rew[cell]);
        }
    }

    // ---- grid barrier ----
    __threadfence();
    __syncthreads();
    if (threadIdx.x == 0) {
        int t = atomicAdd(&g_arrive, 1);
        if (t == (int)gridDim.x - 1) {
            atomicExch(&g_flag, 1);
        } else {
            while (atomicAdd(&g_flag, 0) == 0) { }
        }
    }
    __syncthreads();
    __threadfence();

    // ---- phase 2: normalize visited cells (idempotent stores) ----
    if (active)
        svf[cell] = 1.0f / ((float)g_nvis[b] + EPSV);

    // ---- phase 3: scalar loss (block 0 only) ----
    if (blockIdx.x == 0) {
        int bb = threadIdx.x;
        float et = 0.f, st = 0.f;
        if (bb < B) {
            float es = 0.f, esr = 0.f;
#pragma unroll
            for (int i = 0; i < BPB; i++) {
                es  += g_es [bb * BPB + i];
                esr += g_esr[bb * BPB + i];
            }
            et = esr / (es + EPSV);
            st = g_sr[bb] / ((float)g_nvis[bb] + EPSV);
        }
        __shared__ float se[256], ss[256];
        se[threadIdx.x] = et;
        ss[threadIdx.x] = st;
        __syncthreads();
#pragma unroll
        for (int off = 128; off > 0; off >>= 1) {
            if (threadIdx.x < off) {
                se[threadIdx.x] += se[threadIdx.x + off];
                ss[threadIdx.x] += ss[threadIdx.x + off];
            }
            __syncthreads();
        }
        if (threadIdx.x == 0)
            out_loss[0] = (se[0] - ss[0]) / (float)B;
    }
}

// ---------------------------------------------------------------------------
extern "C" void kernel_launch(void* const* d_in, const int* in_sizes, int n_in,
                              void* d_out, int out_size) {
    const float* gt      = (const float*)d_in[0];  // (B,T,3,3)
    const float* exp_svf = (const float*)d_in[1];  // (B,H,W)
    const float* rew     = (const float*)d_in[2];  // (B,H,W)
    float* out = (float*)d_out;

    int B = in_sizes[1] / (HH * WW);
    int T = in_sizes[0] / (B * 9);
    long grid_elems = (long)B * HH * WW;
    // out layout: [loss(1)][svf(B*H*W)][interp_pts(B*Npts*2)]
    int Npts = (int)(((long)out_size - 1 - grid_elems) / (2L * B));
    int ms = (T > 1 && Npts > 1) ? (Npts - 1) / (T - 1) : 1;
    if (ms < 1) ms = 1;

    float* svf = out + 1;
    float* pts = out + 1 + grid_elems;

    long n  = (long)out_size;
    long n4 = n / 4;                       // out base is 256B-aligned -> float4 OK
    long nblocks = (long)BPB * B;
    long c4 = (n4 + nblocks - 1) / nblocks; // zero-fill chunk per block

    dim3 rg(BPB, B);
    k_main<<<rg, RED_THREADS>>>((const float4*)exp_svf, (const float4*)rew,
                                (float4*)out, out, n4, n, c4);

    int tot = B * Npts;
    int pblocks = (tot + 255) / 256;
    k_pts<<<pblocks, 256>>>(gt, rew, svf, pts, out, B, T, Npts, ms);
}

// round 17
// speedup vs baseline: 1.1509x; 1.0035x over previous
#include <cuda_runtime.h>
#include <cuda_bf16.h>

#define HH 512
#define WW 1024
#define EPSV 1e-5f
#define BPB 16            // reduction blocks per batch (single-wave grid)
#define RED_THREADS 256
#define VPB ((HH * WW / 4) / BPB)      // float4 vectors per reduction block = 8192
#define RED_ITERS (VPB / RED_THREADS)  // 32

// Scratch (no allocations allowed) — sized for up to 128 batches.
__device__ float g_es [128 * BPB];
__device__ float g_esr[128 * BPB];
__device__ int   g_nvis[128];
__device__ float g_sr  [128];

// ---------------------------------------------------------------------------
// K_MAIN: fused (a) zero the [loss][svf] output region (pts region is fully
// overwritten later, no zeroing needed), (b) per-batch partial reductions of
// exp_svf and exp_svf*reward. Interleaved so read AND write streams are in
// flight simultaneously. grid = (BPB, B) = 1024 blocks -> single wave on
// 148 SMs. Streaming cache hints: every byte touched once.
// ---------------------------------------------------------------------------
__global__ void k_main(const float4* __restrict__ e4,
                       const float4* __restrict__ r4,
                       float4* __restrict__ o4,
                       float* __restrict__ out,
                       long nz, long nz4, long c4) {
    int b   = blockIdx.y;
    int blk = blockIdx.x;
    int gid = b * BPB + blk;
    long base  = (long)b * (HH * WW / 4) + (long)blk * VPB;
    long zbase = (long)gid * c4;
    long zend  = zbase + c4; if (zend > nz4) zend = nz4;

    const float4 z = make_float4(0.f, 0.f, 0.f, 0.f);
    float es = 0.f, esr = 0.f;

#pragma unroll 8
    for (int k = 0; k < RED_ITERS; k++) {
        long idx = base + (long)k * RED_THREADS + threadIdx.x;
        float4 e = __ldcs(&e4[idx]);
        float4 r = __ldcs(&r4[idx]);
        long zi = zbase + (long)k * RED_THREADS + threadIdx.x;
        if (zi < zend) __stcs(&o4[zi], z);
        es  += (e.x + e.y) + (e.z + e.w);
        esr += e.x * r.x + e.y * r.y + e.z * r.z + e.w * r.w;
    }
    // leftover zero iterations (chunk may exceed RED_ITERS*256 vectors)
    for (long zi = zbase + (long)RED_ITERS * RED_THREADS + threadIdx.x;
         zi < zend; zi += RED_THREADS)
        __stcs(&o4[zi], z);

    // scalar tail of the zero region (< 4 floats)
    if (gid == 0 && threadIdx.x < (int)(nz - nz4 * 4))
        out[nz4 * 4 + threadIdx.x] = 0.f;
    // per-batch scatter accumulators
    if (gid == gridDim.x * gridDim.y - 1 && threadIdx.x < 128) {
        g_nvis[threadIdx.x] = 0;
        g_sr[threadIdx.x]   = 0.f;
    }

#pragma unroll
    for (int off = 16; off > 0; off >>= 1) {
        es  += __shfl_down_sync(0xFFFFFFFFu, es,  off);
        esr += __shfl_down_sync(0xFFFFFFFFu, esr, off);
    }
    __shared__ float se[RED_THREADS / 32], sm[RED_THREADS / 32];
    int w = threadIdx.x >> 5;
    if ((threadIdx.x & 31) == 0) { se[w] = es; sm[w] = esr; }
    __syncthreads();
    if (threadIdx.x == 0) {
        float a = 0.f, c = 0.f;
#pragma unroll
        for (int i = 0; i < RED_THREADS / 32; i++) { a += se[i]; c += sm[i]; }
        g_es [b * BPB + blk] = a;
        g_esr[b * BPB + blk] = c;
    }
}

// ---------------------------------------------------------------------------
// Point interpolation. Mul-then-add (no FMA) to match JAX's
// start + t*(end-start) rounding so int truncation picks the same cell.
// ---------------------------------------------------------------------------
__device__ __forceinline__ void interp_point(const float* __restrict__ gt,
                                             int b, int p, int T, int Npts,
                                             int ms, float& px, float& py) {
    if (p == Npts - 1) {
        const float* g = gt + ((long)b * T + (T - 1)) * 9;
        px = g[2] * 0.5f;
        py = g[5] * 0.5f;
    } else {
        int s = p / ms;
        int j = p - s * ms;
        const float* g = gt + ((long)b * T + s) * 9;
        float sx = g[2]  * 0.5f, sy = g[5]  * 0.5f;
        float ex = g[11] * 0.5f, ey = g[14] * 0.5f;
        float t = (ms > 1) ? (float)j / (float)(ms - 1) : 0.f;
        px = __fadd_rn(sx, __fmul_rn(t, __fsub_rn(ex, sx)));
        py = __fadd_rn(sy, __fmul_rn(t, __fsub_rn(ey, sy)));
    }
}

__device__ __forceinline__ long point_cell(int b, float px, float py) {
    int xi = (int)fminf(fmaxf(px, 0.f), (float)(HH - 1));
    int yi = (int)fminf(fmaxf(py, 0.f), (float)(WW - 1));
    return (long)b * (HH * WW) + (long)xi * WW + yi;
}

// ---------------------------------------------------------------------------
// K_POINTS: one thread per interpolated point. Writes interp_pts output,
// scatters visitation (dedup via atomicExch), accumulates per-batch nvis and
// sum(reward @ visited cells).
// ---------------------------------------------------------------------------
__global__ void k_points(const float* __restrict__ gt,
                         const float* __restrict__ rew,
                         float* __restrict__ svf,
                         float* __restrict__ pts_out,
                         int B, int T, int Npts, int ms) {
    int idx = blockIdx.x * blockDim.x + threadIdx.x;
    if (idx >= B * Npts) return;
    int b = idx / Npts;
    int p = idx - b * Npts;

    float px, py;
    interp_point(gt, b, p, T, Npts, ms, px, py);

    pts_out[(long)idx * 2]     = px;
    pts_out[(long)idx * 2 + 1] = py;

    long cell = point_cell(b, px, py);
    float old = atomicExch(&svf[cell], 1.0f);
    if (old == 0.0f) {
        atomicAdd(&g_nvis[b], 1);
        atomicAdd(&g_sr[b], rew[cell]);
    }
}

// ---------------------------------------------------------------------------
// K_SCALE_FINAL: (a) overwrite each visited cell with 1/(nvis+eps), reading
// the already-computed points from pts_out with SCALAR loads (pts base sits
// at an odd float offset — vector loads would be misaligned; two contiguous
// 4B loads per thread are still coalesced). Idempotent stores.
// (b) block 0 additionally computes the scalar loss — all its inputs
// (g_es/g_esr from k_main, g_sr/g_nvis from k_points) are ready and L2-hot.
//   loss = mean_b( esr_b/(es_b+eps) ) - mean_b( sr_b/(nvis_b+eps) )
// ---------------------------------------------------------------------------
__global__ void k_scale_final(const float* __restrict__ pts,
                              float* __restrict__ svf,
                              float* __restrict__ out_loss,
                              int B, int Npts) {
    int idx = blockIdx.x * blockDim.x + threadIdx.x;
    if (idx < B * Npts) {
        int b = idx / Npts;
        float px = pts[(long)idx * 2];
        float py = pts[(long)idx * 2 + 1];
        long cell = point_cell(b, px, py);
        svf[cell] = 1.0f / ((float)g_nvis[b] + EPSV);
    }

    if (blockIdx.x == 0) {
        int bb = threadIdx.x;
        float et = 0.f, st = 0.f;
        if (bb < B) {
            float es = 0.f, esr = 0.f;
#pragma unroll
            for (int i = 0; i < BPB; i++) {
                es  += g_es [bb * BPB + i];
                esr += g_esr[bb * BPB + i];
            }
            et = esr / (es + EPSV);
            st = g_sr[bb] / ((float)g_nvis[bb] + EPSV);
        }
        __shared__ float se[256], ss[256];
        se[threadIdx.x] = et;
        ss[threadIdx.x] = st;
        __syncthreads();
#pragma unroll
        for (int off = 128; off > 0; off >>= 1) {
            if (threadIdx.x < off) {
                se[threadIdx.x] += se[threadIdx.x + off];
                ss[threadIdx.x] += ss[threadIdx.x + off];
            }
            __syncthreads();
        }
        if (threadIdx.x == 0)
            out_loss[0] = (se[0] - ss[0]) / (float)B;
    }
}

// ---------------------------------------------------------------------------
extern "C" void kernel_launch(void* const* d_in, const int* in_sizes, int n_in,
                              void* d_out, int out_size) {
    const float* gt      = (const float*)d_in[0];  // (B,T,3,3)
    const float* exp_svf = (const float*)d_in[1];  // (B,H,W)
    const float* rew     = (const float*)d_in[2];  // (B,H,W)
    float* out = (float*)d_out;

    int B = in_sizes[1] / (HH * WW);
    int T = in_sizes[0] / (B * 9);
    long grid_elems = (long)B * HH * WW;
    // out layout: [loss(1)][svf(B*H*W)][interp_pts(B*Npts*2)]
    int Npts = (int)(((long)out_size - 1 - grid_elems) / (2L * B));
    int ms = (T > 1 && Npts > 1) ? (Npts - 1) / (T - 1) : 1;
    if (ms < 1) ms = 1;

    float* svf = out + 1;
    float* pts = out + 1 + grid_elems;

    long nz  = 1 + grid_elems;             // zero only [loss][svf]
    long nz4 = nz / 4;                     // out base is 256B-aligned -> float4 OK
    long nblocks = (long)BPB * B;
    long c4 = (nz4 + nblocks - 1) / nblocks; // zero-fill chunk per block

    dim3 rg(BPB, B);
    k_main<<<rg, RED_THREADS>>>((const float4*)exp_svf, (const float4*)rew,
                                (float4*)out, out, nz, nz4, c4);

    int tot = B * Npts;
    int pblocks = (tot + 255) / 256;
    k_points<<<pblocks, 256>>>(gt, rew, svf, pts, B, T, Npts, ms);
    k_scale_final<<<pblocks, 256>>>(pts, svf, out, B, Npts);
}